// round 5
// baseline (speedup 1.0000x reference)
#include <cuda_runtime.h>
#include <cuda_bf16.h>

// Problem constants (fixed by the reference setup_inputs):
//   f  : (B=32, H=512, W=512) float32
//   K  : (5, 5, H, W)         float32   (per-pixel kernels, shared over batch)
//   dt : (B,)                 float32
//   out: (B, H, W)            float32 = relu(f + df * dt[b])
//   df[b,y,x] = sum_{i,j} K[i,j,y,x] * f_pad[b, y+i, x+j]  (zero pad=2)

#define B_  32
#define H_  512
#define W_  512
#define KS  5
#define RAD 2
#define TH  16
#define TW  16
// Shared tile: (TH+4) rows, row stride 48 floats (48 mod 32 == 16 ->
// lanes 0-15 (row r) and lanes 16-31 (row r+1) hit disjoint bank sets).
#define SSTRIDE 48

__global__ __launch_bounds__(256, 4)
void op2d_kernel(const float* __restrict__ f,
                 const float* __restrict__ K,
                 const float* __restrict__ dt,
                 float* __restrict__ out)
{
    __shared__ float tile[(TH + 2 * RAD) * SSTRIDE];

    const int tid = threadIdx.x;          // 0..255
    const int tx  = tid & (TW - 1);       // 0..15
    const int ty  = tid >> 4;             // 0..15
    const int bx  = blockIdx.x * TW;
    const int by  = blockIdx.y * TH;
    const int x   = bx + tx;
    const int y   = by + ty;

    // ---- Load this pixel's 25 kernel taps into registers (reused for all 32 b)
    const int pix = y * W_ + x;
    float kv[KS * KS];
#pragma unroll
    for (int t = 0; t < KS * KS; ++t)
        kv[t] = __ldg(&K[t * (H_ * W_) + pix]);

    const float* fb  = f + pix;                 // advanced per-b by H*W
    float*       ob  = out + pix;

    for (int b = 0; b < B_; ++b) {
        // ---- Cooperative staged load of (TH+4)x(TW+4) f tile (zero padded)
        const float* fplane = f + b * (H_ * W_);
#pragma unroll
        for (int s = tid; s < (TH + 2 * RAD) * (TW + 2 * RAD); s += 256) {
            const int sy = s / (TW + 2 * RAD);
            const int sx = s - sy * (TW + 2 * RAD);
            const int gy = by - RAD + sy;
            const int gx = bx - RAD + sx;
            float v = 0.0f;
            if ((unsigned)gy < (unsigned)H_ && (unsigned)gx < (unsigned)W_)
                v = __ldg(&fplane[gy * W_ + gx]);
            tile[sy * SSTRIDE + sx] = v;
        }
        __syncthreads();

        // ---- 25-tap accumulate from shared memory
        float acc = 0.0f;
#pragma unroll
        for (int i = 0; i < KS; ++i) {
#pragma unroll
            for (int j = 0; j < KS; ++j) {
                acc = fmaf(kv[i * KS + j],
                           tile[(ty + i) * SSTRIDE + (tx + j)], acc);
            }
        }
        const float fc = tile[(ty + RAD) * SSTRIDE + (tx + RAD)];
        const float o  = fmaf(acc, __ldg(&dt[b]), fc);
        ob[b * (H_ * W_)] = fmaxf(o, 0.0f);

        __syncthreads();   // protect tile before next b overwrites it
    }
    (void)fb;
}

extern "C" void kernel_launch(void* const* d_in, const int* in_sizes, int n_in,
                              void* d_out, int out_size)
{
    const float* f  = (const float*)d_in[0];   // 32*512*512
    const float* K  = (const float*)d_in[1];   // 5*5*512*512
    const float* dt = (const float*)d_in[2];   // 32
    float* out = (float*)d_out;

    dim3 grid(W_ / TW, H_ / TH);   // 32 x 32 blocks
    dim3 block(256);
    op2d_kernel<<<grid, block>>>(f, K, dt, out);
}

// round 6
// speedup vs baseline: 1.4560x; 1.4560x over previous
#include <cuda_runtime.h>
#include <cuda_bf16.h>

// f  : (B=32, H=512, W=512) f32
// K  : (5, 5, H, W)         f32  (per-pixel kernels, shared over batch -> registers)
// dt : (B,)                 f32
// out = relu(f + conv5x5_perpixel(f) * dt[b])

#define B_    32
#define H_    512
#define W_    512
#define HW_   (H_ * W_)
#define KS    5
#define RAD   2
#define TW    32          // tile width  (pixels)
#define TH    16          // tile height (pixels)
#define TILE_W (TW + 2*RAD)   // 36
#define TILE_H (TH + 2*RAD)   // 20
#define SSTR  37          // odd stride -> adjacent smem rows use opposite bank parity
#define TILE_ELEMS (TILE_W * TILE_H)   // 720
#define NLD   3           // ceil(720 / 256)

__global__ __launch_bounds__(256, 3)
void op2d_kernel(const float* __restrict__ f,
                 const float* __restrict__ K,
                 const float* __restrict__ dt,
                 float* __restrict__ out)
{
    __shared__ float buf[2][TILE_H * SSTR];

    const int tid = threadIdx.x;           // 0..255
    const int tx  = tid & 15;              // 0..15  -> covers x0 = 2*tx, 2*tx+1
    const int ty  = tid >> 4;              // 0..15
    const int bx  = blockIdx.x * TW;
    const int by  = blockIdx.y * TH;
    const int x0  = bx + tx * 2;
    const int y   = by + ty;
    const int pix = y * W_ + x0;           // even -> float2-aligned

    // ---- 25 taps x 2 pixels of K into registers (reused for all 32 batches)
    float kv0[KS * KS], kv1[KS * KS];
#pragma unroll
    for (int t = 0; t < KS * KS; ++t) {
        const float2 kk = __ldg((const float2*)(K + t * HW_ + pix));
        kv0[t] = kk.x;
        kv1[t] = kk.y;
    }

    // ---- batch-invariant staged-load coordinates + predicates
    int  goff [NLD];
    int  soff [NLD];
    bool valid[NLD];
    bool inuse[NLD];
#pragma unroll
    for (int k = 0; k < NLD; ++k) {
        const int s  = tid + k * 256;
        inuse[k] = (s < TILE_ELEMS);
        const int sy = s / TILE_W;
        const int sx = s - sy * TILE_W;
        const int gy = by - RAD + sy;
        const int gx = bx - RAD + sx;
        valid[k] = inuse[k] && (unsigned)gy < (unsigned)H_ && (unsigned)gx < (unsigned)W_;
        goff[k]  = valid[k] ? gy * W_ + gx : 0;
        soff[k]  = sy * SSTR + sx;
    }

    // ---- prologue: stage batch 0
    float pre[NLD];
#pragma unroll
    for (int k = 0; k < NLD; ++k)
        pre[k] = valid[k] ? __ldg(&f[goff[k]]) : 0.0f;
#pragma unroll
    for (int k = 0; k < NLD; ++k)
        if (inuse[k]) buf[0][soff[k]] = pre[k];
    __syncthreads();

    const int rbase = ty * SSTR + tx * 2;
    int cur = 0;

    for (int b = 0; b < B_; ++b) {
        // -- prefetch batch b+1 (latency hidden under this batch's compute)
        if (b + 1 < B_) {
            const float* fn = f + (b + 1) * HW_;
#pragma unroll
            for (int k = 0; k < NLD; ++k)
                pre[k] = valid[k] ? __ldg(&fn[goff[k]]) : 0.0f;
        }

        // -- 5x5 per-pixel conv, 2 pixels/thread, taps shared via 6-wide row regs
        const float* __restrict__ tb = buf[cur];
        float acc0 = 0.0f, acc1 = 0.0f;
        float fc0 = 0.0f, fc1 = 0.0f;
#pragma unroll
        for (int i = 0; i < KS; ++i) {
            float r[TW >= 0 ? 6 : 6];
#pragma unroll
            for (int c = 0; c < 6; ++c)
                r[c] = tb[rbase + i * SSTR + c];
            if (i == RAD) { fc0 = r[2]; fc1 = r[3]; }
#pragma unroll
            for (int j = 0; j < KS; ++j) {
                acc0 = fmaf(kv0[i * KS + j], r[j],     acc0);
                acc1 = fmaf(kv1[i * KS + j], r[j + 1], acc1);
            }
        }

        const float dtb = __ldg(&dt[b]);
        float2 o;
        o.x = fmaxf(fmaf(acc0, dtb, fc0), 0.0f);
        o.y = fmaxf(fmaf(acc1, dtb, fc1), 0.0f);
        *(float2*)(out + b * HW_ + pix) = o;

        // -- commit prefetched tile into the other buffer, single barrier
        const int nxt = cur ^ 1;
        if (b + 1 < B_) {
#pragma unroll
            for (int k = 0; k < NLD; ++k)
                if (inuse[k]) buf[nxt][soff[k]] = pre[k];
        }
        __syncthreads();
        cur = nxt;
    }
}

extern "C" void kernel_launch(void* const* d_in, const int* in_sizes, int n_in,
                              void* d_out, int out_size)
{
    const float* f  = (const float*)d_in[0];
    const float* K  = (const float*)d_in[1];
    const float* dt = (const float*)d_in[2];
    float* out = (float*)d_out;

    dim3 grid(W_ / TW, H_ / TH);   // 16 x 32 = 512 blocks
    dim3 block(256);
    op2d_kernel<<<grid, block>>>(f, K, dt, out);
}

// round 7
// speedup vs baseline: 2.3340x; 1.6031x over previous
#include <cuda_runtime.h>
#include <cuda_bf16.h>

// f  : (B=32, H=512, W=512) f32
// K  : (5, 5, H, W)         f32  (per-pixel kernels, shared over batch -> registers)
// dt : (B,)                 f32
// out = relu(f + conv5x5_perpixel(f) * dt[b])
//
// Strategy: 2 px/thread (x), 50 K taps in regs for the whole kernel.
// Batch dimension tiled NB=4 per pass (8 passes), all 4 batch tiles in smem
// -> 8 independent FMA chains/thread, LDS.64 row loads, cp.async staging
// with zero-fill for the halo, double-buffered, 1 barrier per pass.

#define B_    32
#define H_    512
#define W_    512
#define HW_   (H_ * W_)
#define KS    5
#define RAD   2
#define TW    32
#define TH    16
#define TILE_W (TW + 2*RAD)        // 36
#define TILE_H (TH + 2*RAD)        // 20
#define SSTR   38                  // even: float2-aligned rows, conflict-free phases
#define PLANE  (TILE_H * SSTR)     // 760 floats
#define TILE_ELEMS (TILE_W * TILE_H)  // 720
#define NLD    3                   // ceil(720/256)
#define NB     4
#define NPASS  (B_ / NB)           // 8

__device__ __forceinline__ void cp4(unsigned sa, const float* g, int sz) {
    // 4-byte async copy; sz=0 -> zero-fill (halo out-of-bounds)
    asm volatile("cp.async.ca.shared.global [%0], [%1], 4, %2;\n"
                 :: "r"(sa), "l"(g), "r"(sz));
}
__device__ __forceinline__ void cp_commit() { asm volatile("cp.async.commit_group;\n" ::); }
__device__ __forceinline__ void cp_wait0()  { asm volatile("cp.async.wait_group 0;\n" ::); }

__global__ __launch_bounds__(256, 3)
void op2d_kernel(const float* __restrict__ f,
                 const float* __restrict__ K,
                 const float* __restrict__ dt,
                 float* __restrict__ out)
{
    __shared__ __align__(16) float buf[2][NB][PLANE];

    const int tid = threadIdx.x;          // 0..255
    const int tx  = tid & 15;             // px pair x
    const int ty  = tid >> 4;
    const int bx  = blockIdx.x * TW;
    const int by  = blockIdx.y * TH;
    const int x0  = bx + tx * 2;
    const int y   = by + ty;
    const int pix = y * W_ + x0;          // even -> float2 aligned

    // ---- 25 taps x 2 px in registers, reused across all 32 batches
    float2 kv[KS * KS];
#pragma unroll
    for (int t = 0; t < KS * KS; ++t)
        kv[t] = __ldg((const float2*)(K + t * HW_ + pix));

    // ---- batch-invariant staging coords (cp.async, zero-fill for halo)
    int      goff[NLD];
    int      szb [NLD];
    unsigned sadr[NLD];
    bool     inuse[NLD];
    const unsigned sbase = (unsigned)__cvta_generic_to_shared(&buf[0][0][0]);
#pragma unroll
    for (int k = 0; k < NLD; ++k) {
        const int s  = tid + k * 256;
        inuse[k] = (s < TILE_ELEMS);
        const int sy = s / TILE_W;
        const int sx = s - sy * TILE_W;
        const int gy = by - RAD + sy;
        const int gx = bx - RAD + sx;
        const bool v = inuse[k] && (unsigned)gy < (unsigned)H_ && (unsigned)gx < (unsigned)W_;
        goff[k] = v ? gy * W_ + gx : 0;
        szb[k]  = v ? 4 : 0;
        sadr[k] = sbase + (unsigned)(sy * SSTR + sx) * 4u;
    }

    // ---- prologue: stage pass 0 into buffer 0
    {
        const float* fp = f;
#pragma unroll
        for (int b = 0; b < NB; ++b)
#pragma unroll
            for (int k = 0; k < NLD; ++k)
                if (inuse[k])
                    cp4(sadr[k] + (unsigned)(b * PLANE) * 4u, fp + b * HW_ + goff[k], szb[k]);
        cp_commit();
        cp_wait0();
    }
    __syncthreads();

    const int rbase = ty * SSTR + tx * 2;
    int cur = 0;

    for (int pass = 0; pass < NPASS; ++pass) {
        const int nxt = cur ^ 1;

        // -- stage next pass (overlaps with this pass's compute)
        if (pass + 1 < NPASS) {
            const float* fp = f + (pass + 1) * NB * HW_;
            const unsigned boff = (unsigned)(nxt * NB * PLANE) * 4u;
#pragma unroll
            for (int b = 0; b < NB; ++b)
#pragma unroll
                for (int k = 0; k < NLD; ++k)
                    if (inuse[k])
                        cp4(sadr[k] + boff + (unsigned)(b * PLANE) * 4u,
                            fp + b * HW_ + goff[k], szb[k]);
            cp_commit();
        }

        // -- 5x5 per-pixel conv: 4 batches x 2 px = 8 independent chains
        float acc0[NB], acc1[NB];
#pragma unroll
        for (int b = 0; b < NB; ++b) { acc0[b] = 0.0f; acc1[b] = 0.0f; }

#pragma unroll
        for (int i = 0; i < KS; ++i) {
#pragma unroll
            for (int b = 0; b < NB; ++b) {
                const float* tb = buf[cur][b] + rbase + i * SSTR;
                const float2 ra = *(const float2*)(tb + 0);
                const float2 rb = *(const float2*)(tb + 2);
                const float2 rc = *(const float2*)(tb + 4);
                acc0[b] = fmaf(kv[i*KS+0].x, ra.x, acc0[b]);
                acc1[b] = fmaf(kv[i*KS+0].y, ra.y, acc1[b]);
                acc0[b] = fmaf(kv[i*KS+1].x, ra.y, acc0[b]);
                acc1[b] = fmaf(kv[i*KS+1].y, rb.x, acc1[b]);
                acc0[b] = fmaf(kv[i*KS+2].x, rb.x, acc0[b]);
                acc1[b] = fmaf(kv[i*KS+2].y, rb.y, acc1[b]);
                acc0[b] = fmaf(kv[i*KS+3].x, rb.y, acc0[b]);
                acc1[b] = fmaf(kv[i*KS+3].y, rc.x, acc1[b]);
                acc0[b] = fmaf(kv[i*KS+4].x, rc.x, acc0[b]);
                acc1[b] = fmaf(kv[i*KS+4].y, rc.y, acc1[b]);
            }
        }

        // -- epilogue: re-read center f, scale by dt, relu, coalesced float2 store
        const int b0 = pass * NB;
#pragma unroll
        for (int b = 0; b < NB; ++b) {
            const float2 c  = *(const float2*)(buf[cur][b] + rbase + RAD * SSTR + RAD);
            const float dtb = __ldg(&dt[b0 + b]);
            float2 o;
            o.x = fmaxf(fmaf(acc0[b], dtb, c.x), 0.0f);
            o.y = fmaxf(fmaf(acc1[b], dtb, c.y), 0.0f);
            *(float2*)(out + (b0 + b) * HW_ + pix) = o;
        }

        if (pass + 1 < NPASS) cp_wait0();
        __syncthreads();
        cur = nxt;
    }
}

extern "C" void kernel_launch(void* const* d_in, const int* in_sizes, int n_in,
                              void* d_out, int out_size)
{
    const float* f  = (const float*)d_in[0];
    const float* K  = (const float*)d_in[1];
    const float* dt = (const float*)d_in[2];
    float* out = (float*)d_out;

    dim3 grid(W_ / TW, H_ / TH);   // 16 x 32 = 512 blocks
    dim3 block(256);
    op2d_kernel<<<grid, block>>>(f, K, dt, out);
}